// round 1
// baseline (speedup 1.0000x reference)
#include <cuda_runtime.h>

// Problem constants
#define BB 64
#define NN 511
#define DD 256
#define MR (BB*NN)   // 32704 rows

// ---------------- scratch (device globals; no allocation allowed) -------------
__device__ float g_H [MR*DD];
__device__ float g_Ek[MR*DD];
__device__ float g_Ev[MR*DD];
__device__ float g_Hq[MR*DD];
__device__ float g_Hk[MR*DD];
__device__ float g_Hv[MR*DD];
__device__ float g_O [MR*DD];
__device__ float g_state[BB*DD];
__device__ float g_Sk[BB*DD];
__device__ float g_Sv[BB*DD];
__device__ float g_q2[BB*DD];
__device__ float g_o2[BB*DD];

// ---------------- embedding: e = emb[wordid*mask]*mask ; h = e ---------------
__global__ void embed_kernel(const int* __restrict__ wordid, const int* __restrict__ mask,
                             const float* __restrict__ emb, float* __restrict__ H){
    long node = blockIdx.x;
    int  t    = threadIdx.x;
    int wid = wordid[node];
    int m   = mask[node];
    H[node*DD + t] = emb[(long)(wid*m)*DD + t] * (float)m;
}

// ---------------- state init: state[b,:] = mean over nodes of e --------------
__global__ void initstate_kernel(const float* __restrict__ H, float* __restrict__ state){
    int b = blockIdx.x, t = threadIdx.x;
    const float* p = H + (long)b*NN*DD + t;
    float s = 0.f;
    for(int i=0;i<NN;i++) s += p[(long)i*DD];
    state[b*DD + t] = s * (1.f/(float)NN);
}

// ---------------- SGEMM: C[M,256] = A[M,256] @ W[256,256] + bias -------------
// BM=BN=64, BK=16, 256 threads, 4x4 per thread.
__global__ void sgemm_kernel(const float* __restrict__ A, const float* __restrict__ W,
                             const float* __restrict__ bias, float* __restrict__ C){
    __shared__ float As[16][68];   // stored transposed: As[k][m], padded (68*4=272B, 16B aligned rows)
    __shared__ float Bs[16][64];
    int tid = threadIdx.x;
    long bm = (long)blockIdx.y * 64;
    int  bn = blockIdx.x * 64;
    int ar = tid >> 2,  ac = (tid & 3)  * 4;   // A tile: 64 rows x 16 cols
    int br = tid >> 4,  bc = (tid & 15) * 4;   // B tile: 16 rows x 64 cols
    int tx = tid & 15,  ty = tid >> 4;
    float acc[4][4] = {};
    const float* Ap = A + (bm + ar)*256 + ac;
    const float* Wp = W + (long)br*256 + bn + bc;
    for(int k0 = 0; k0 < 256; k0 += 16){
        float4 av = *(const float4*)(Ap + k0);
        As[ac+0][ar] = av.x; As[ac+1][ar] = av.y;
        As[ac+2][ar] = av.z; As[ac+3][ar] = av.w;
        *(float4*)&Bs[br][bc] = *(const float4*)(Wp + (long)k0*256);
        __syncthreads();
#pragma unroll
        for(int kk = 0; kk < 16; kk++){
            float a[4], b[4];
#pragma unroll
            for(int i=0;i<4;i++) a[i] = As[kk][ty*4+i];
#pragma unroll
            for(int j=0;j<4;j++) b[j] = Bs[kk][tx*4+j];
#pragma unroll
            for(int i=0;i<4;i++)
#pragma unroll
                for(int j=0;j<4;j++) acc[i][j] += a[i]*b[j];
        }
        __syncthreads();
    }
#pragma unroll
    for(int i=0;i<4;i++){
        long row = bm + ty*4 + i;
        float4 o;
        o.x = acc[i][0] + bias[bn + tx*4 + 0];
        o.y = acc[i][1] + bias[bn + tx*4 + 1];
        o.z = acc[i][2] + bias[bn + tx*4 + 2];
        o.w = acc[i][3] + bias[bn + tx*4 + 3];
        *(float4*)(C + row*256 + bn + tx*4) = o;
    }
}

// ------------- step-1 attention: per node, 5 keys [cl,cr,h,e,s] --------------
// One block per (b,node); warp w == head w (DK=32 dims per head).
__global__ void attn1_kernel(const float* __restrict__ Hq, const float* __restrict__ Hk,
                             const float* __restrict__ Hv,
                             const float* __restrict__ Ek, const float* __restrict__ Ev,
                             const float* __restrict__ Sk, const float* __restrict__ Sv,
                             const float* __restrict__ k1b, const float* __restrict__ v1b,
                             float* __restrict__ O){
    int  nb   = blockIdx.x;          // b*511 + node
    int  node = nb % NN;
    int  b    = nb / NN;
    int  t    = threadIdx.x;
    long base = (long)nb * DD;
    bool internal = node < 255;      // 2*node+1 < 511
    long lb = (long)(nb + node + 1) * DD;   // left child row
    long rb = lb + DD;                      // right child row

    float q  = Hq[base + t];
    float s[5];
    s[0] = q * (internal ? Hk[lb + t] : k1b[t]);
    s[1] = q * (internal ? Hk[rb + t] : k1b[t]);
    s[2] = q * Hk[base + t];
    s[3] = q * Ek[base + t];
    s[4] = q * Sk[b*DD + t];
#pragma unroll
    for(int o = 16; o; o >>= 1){
#pragma unroll
        for(int j=0;j<5;j++) s[j] += __shfl_xor_sync(0xffffffffu, s[j], o);
    }
    const float scale = 0.17677669529663687f;   // 1/sqrt(32)
    float mx = -1e30f;
#pragma unroll
    for(int j=0;j<5;j++){ s[j] *= scale; mx = fmaxf(mx, s[j]); }
    float w[5], sum = 0.f;
#pragma unroll
    for(int j=0;j<5;j++){ w[j] = __expf(s[j]-mx); sum += w[j]; }
    float inv = 1.f / sum;
    float v0 = internal ? Hv[lb + t] : v1b[t];
    float v1 = internal ? Hv[rb + t] : v1b[t];
    float v2 = Hv[base + t];
    float v3 = Ev[base + t];
    float v4 = Sv[b*DD + t];
    O[base + t] = (w[0]*v0 + w[1]*v1 + w[2]*v2 + w[3]*v3 + w[4]*v4) * inv;
}

// ------------- relu + layernorm (torch semantics: unbiased std, eps on std) --
__global__ void relu_ln_kernel(const float* __restrict__ X, const float* __restrict__ gam,
                               const float* __restrict__ bet, float* __restrict__ Y){
    long row = blockIdx.x;
    int  t   = threadIdx.x;
    __shared__ float wsh[8];
    __shared__ float stat[2];
    float x = fmaxf(X[row*DD + t], 0.f);

    float v = x;
#pragma unroll
    for(int o=16;o;o>>=1) v += __shfl_xor_sync(0xffffffffu, v, o);
    if((t&31)==0) wsh[t>>5] = v;
    __syncthreads();
    if(t < 32){
        float r = (t < 8) ? wsh[t] : 0.f;
#pragma unroll
        for(int o=4;o;o>>=1) r += __shfl_xor_sync(0xffffffffu, r, o);
        if(t==0) stat[0] = r;
    }
    __syncthreads();
    float mean = stat[0] * (1.f/256.f);
    float dx = x - mean;

    v = dx*dx;
#pragma unroll
    for(int o=16;o;o>>=1) v += __shfl_xor_sync(0xffffffffu, v, o);
    if((t&31)==0) wsh[t>>5] = v;
    __syncthreads();
    if(t < 32){
        float r = (t < 8) ? wsh[t] : 0.f;
#pragma unroll
        for(int o=4;o;o>>=1) r += __shfl_xor_sync(0xffffffffu, r, o);
        if(t==0) stat[1] = r;
    }
    __syncthreads();
    float sd = sqrtf(stat[1] * (1.f/255.f));   // unbiased (ddof=1)
    Y[row*DD + t] = gam[t] * dx / (sd + 1e-6f) + bet[t];
}

// ------------- step-2 attention: state attends over 511 h rows ---------------
// (state->state slot is masked to -1e9 in the reference => exactly weight 0)
// One block per (b,head), 256 threads.
__global__ void attn2_kernel(const float* __restrict__ Q2, const float* __restrict__ K2,
                             const float* __restrict__ V2, float* __restrict__ O2){
    int b = blockIdx.x >> 3, head = blockIdx.x & 7;
    int t = threadIdx.x;
    __shared__ float sc[NN];
    __shared__ float qs[32];
    __shared__ float red[8][33];
    __shared__ float wsh[8];
    __shared__ float stat[2];
    if(t < 32) qs[t] = Q2[b*DD + head*32 + t];
    __syncthreads();

    const float scale = 0.17677669529663687f;
    float lm = -1e30f;
    for(int i = t; i < NN; i += 256){
        const float* kp = K2 + ((long)(b*NN + i))*DD + head*32;
        float d = 0.f;
#pragma unroll
        for(int j=0;j<32;j++) d += qs[j]*kp[j];
        d *= scale;
        sc[i] = d;
        lm = fmaxf(lm, d);
    }
#pragma unroll
    for(int o=16;o;o>>=1) lm = fmaxf(lm, __shfl_xor_sync(0xffffffffu, lm, o));
    if((t&31)==0) wsh[t>>5] = lm;
    __syncthreads();
    if(t < 32){
        float r = (t < 8) ? wsh[t] : -1e30f;
#pragma unroll
        for(int o=4;o;o>>=1) r = fmaxf(r, __shfl_xor_sync(0xffffffffu, r, o));
        if(t==0) stat[0] = r;
    }
    __syncthreads();
    float mx = stat[0];
    float ls = 0.f;
    for(int i = t; i < NN; i += 256){ float w = __expf(sc[i]-mx); sc[i] = w; ls += w; }
#pragma unroll
    for(int o=16;o;o>>=1) ls += __shfl_xor_sync(0xffffffffu, ls, o);
    if((t&31)==0) wsh[t>>5] = ls;
    __syncthreads();          // also guarantees all sc[] exp-writes are visible
    if(t < 32){
        float r = (t < 8) ? wsh[t] : 0.f;
#pragma unroll
        for(int o=4;o;o>>=1) r += __shfl_xor_sync(0xffffffffu, r, o);
        if(t==0) stat[1] = r;
    }
    __syncthreads();
    float inv = 1.f / stat[1];

    int g = t >> 5, lane = t & 31;
    float acc = 0.f;
    for(int i = g; i < NN; i += 8)
        acc += sc[i] * V2[((long)(b*NN + i))*DD + head*32 + lane];
    red[g][lane] = acc;
    __syncthreads();
    if(t < 32){
        float s2 = 0.f;
#pragma unroll
        for(int gg=0; gg<8; gg++) s2 += red[gg][t];
        O2[b*DD + head*32 + t] = s2 * inv;
    }
}

// ------------- final: logits = H @ linw[256,5] + linb -----------------------
__global__ void logits_kernel(const float* __restrict__ H, const float* __restrict__ linw,
                              const float* __restrict__ linb, float* __restrict__ out){
    __shared__ float w[DD*5];
    int t = threadIdx.x;
    for(int i = t; i < DD*5; i += 256) w[i] = linw[i];
    __syncthreads();
    int warp = t >> 5, lane = t & 31;
    long row = (long)blockIdx.x*8 + warp;   // MR divisible by 8
    const float* hp = H + row*DD;
    float hr[8];
#pragma unroll
    for(int k=0;k<8;k++) hr[k] = hp[lane + 32*k];
#pragma unroll
    for(int c=0;c<5;c++){
        float a = 0.f;
#pragma unroll
        for(int k=0;k<8;k++) a += hr[k] * w[(lane+32*k)*5 + c];
#pragma unroll
        for(int o=16;o;o>>=1) a += __shfl_xor_sync(0xffffffffu, a, o);
        if(lane==0) out[row*5 + c] = a + linb[c];
    }
}

// ------------------------------- host side -----------------------------------
extern "C" void kernel_launch(void* const* d_in, const int* in_sizes, int n_in,
                              void* d_out, int out_size){
    const int*   wordid = (const int*)  d_in[0];
    const int*   mask   = (const int*)  d_in[1];
    const float* emb    = (const float*)d_in[2];
    const float* q1w=(const float*)d_in[3],  *q1b=(const float*)d_in[4];
    const float* k1w=(const float*)d_in[5],  *k1b=(const float*)d_in[6];
    const float* v1w=(const float*)d_in[7],  *v1b=(const float*)d_in[8];
    const float* o1w=(const float*)d_in[9],  *o1b=(const float*)d_in[10];
    const float* q2w=(const float*)d_in[11], *q2b=(const float*)d_in[12];
    const float* k2w=(const float*)d_in[13], *k2b=(const float*)d_in[14];
    const float* v2w=(const float*)d_in[15], *v2b=(const float*)d_in[16];
    const float* o2w=(const float*)d_in[17], *o2b=(const float*)d_in[18];
    const float* ln1g=(const float*)d_in[19],*ln1bb=(const float*)d_in[20];
    const float* ln2g=(const float*)d_in[21],*ln2bb=(const float*)d_in[22];
    const float* linw=(const float*)d_in[23],*linb=(const float*)d_in[24];
    float* out = (float*)d_out;

    float *H,*Ek,*Ev,*Hq,*Hk,*Hv,*O,*state,*Sk,*Sv,*q2,*o2;
    cudaGetSymbolAddress((void**)&H,  g_H);
    cudaGetSymbolAddress((void**)&Ek, g_Ek);
    cudaGetSymbolAddress((void**)&Ev, g_Ev);
    cudaGetSymbolAddress((void**)&Hq, g_Hq);
    cudaGetSymbolAddress((void**)&Hk, g_Hk);
    cudaGetSymbolAddress((void**)&Hv, g_Hv);
    cudaGetSymbolAddress((void**)&O,  g_O);
    cudaGetSymbolAddress((void**)&state, g_state);
    cudaGetSymbolAddress((void**)&Sk, g_Sk);
    cudaGetSymbolAddress((void**)&Sv, g_Sv);
    cudaGetSymbolAddress((void**)&q2, g_q2);
    cudaGetSymbolAddress((void**)&o2, g_o2);

    dim3 gBig(4, MR/64);   // N tiles x M tiles
    dim3 gSm (4, 1);       // M = 64 rows

    embed_kernel    <<<MR, 256>>>(wordid, mask, emb, H);           // h = e
    initstate_kernel<<<BB, 256>>>(H, state);                       // state = mean(e)
    sgemm_kernel<<<gBig,256>>>(H, k1w, k1b, Ek);                   // e-slot keys (once)
    sgemm_kernel<<<gBig,256>>>(H, v1w, v1b, Ev);                   // e-slot values (once)

    for(int it = 0; it < 5; it++){
        // step 1: per-node attention over [cl, cr, h, e, s]
        sgemm_kernel<<<gBig,256>>>(H, q1w, q1b, Hq);
        sgemm_kernel<<<gBig,256>>>(H, k1w, k1b, Hk);
        sgemm_kernel<<<gBig,256>>>(H, v1w, v1b, Hv);
        sgemm_kernel<<<gSm ,256>>>(state, k1w, k1b, Sk);
        sgemm_kernel<<<gSm ,256>>>(state, v1w, v1b, Sv);
        attn1_kernel<<<MR, 256>>>(Hq, Hk, Hv, Ek, Ev, Sk, Sv, k1b, v1b, O);
        sgemm_kernel<<<gBig,256>>>(O, o1w, o1b, Hq);               // reuse Hq as o1 result
        relu_ln_kernel<<<MR, 256>>>(Hq, ln1g, ln1bb, H);

        // step 2: state attends over h (state slot exactly masked out)
        sgemm_kernel<<<gBig,256>>>(H, k2w, k2b, Hk);
        sgemm_kernel<<<gBig,256>>>(H, v2w, v2b, Hv);
        sgemm_kernel<<<gSm ,256>>>(state, q2w, q2b, q2);
        attn2_kernel<<<BB*8, 256>>>(q2, Hk, Hv, o2);
        sgemm_kernel<<<gSm ,256>>>(o2, o2w, o2b, q2);              // reuse q2 as o2 result
        relu_ln_kernel<<<BB, 256>>>(q2, ln2g, ln2bb, state);
    }

    logits_kernel<<<MR/8, 256>>>(H, linw, linb, out);
}

// round 2
// speedup vs baseline: 1.7738x; 1.7738x over previous
#include <cuda_runtime.h>
#include <cuda_bf16.h>
#include <stdint.h>

// Problem constants
#define BB 64
#define NN 511
#define DD 256
#define MR (BB*NN)   // 32704 rows

// ---------------- scratch (device globals; no allocation allowed) -------------
__device__ float g_H [MR*DD];
__device__ float g_Ek[MR*DD];
__device__ float g_Ev[MR*DD];
__device__ float g_Hq[MR*DD];
__device__ float g_Hk[MR*DD];
__device__ float g_Hv[MR*DD];
__device__ float g_O [MR*DD];
__device__ float g_state[BB*DD];
__device__ float g_Sk[BB*DD];
__device__ float g_Sv[BB*DD];
__device__ float g_q2[BB*DD];
__device__ float g_o2[BB*DD];
// bf16 split operands for tensor-core GEMMs
__device__ __nv_bfloat16 g_Hhi[MR*DD];
__device__ __nv_bfloat16 g_Hlo[MR*DD];
__device__ __nv_bfloat16 g_Ohi[MR*DD];
__device__ __nv_bfloat16 g_Olo[MR*DD];
__device__ __nv_bfloat16 g_Whi[6*DD*DD];
__device__ __nv_bfloat16 g_Wlo[6*DD*DD];

__device__ __forceinline__ void split_bf16(float x, __nv_bfloat16& h, __nv_bfloat16& l){
    h = __float2bfloat16_rn(x);
    l = __float2bfloat16_rn(x - __bfloat162float(h));
}

// ---------------- weight split: W fp32 -> (hi, lo) bf16 ----------------------
__global__ void wsplit_kernel(const float* __restrict__ W, __nv_bfloat16* __restrict__ hi,
                              __nv_bfloat16* __restrict__ lo){
    int i = blockIdx.x*256 + threadIdx.x;
    split_bf16(W[i], hi[i], lo[i]);
}

// ---------------- embedding: e = emb[wordid*mask]*mask ; h = e ---------------
__global__ void embed_kernel(const int* __restrict__ wordid, const int* __restrict__ mask,
                             const float* __restrict__ emb, float* __restrict__ H,
                             __nv_bfloat16* __restrict__ Hhi, __nv_bfloat16* __restrict__ Hlo){
    long node = blockIdx.x;
    int  t    = threadIdx.x;
    int wid = wordid[node];
    int m   = mask[node];
    float v = emb[(long)(wid*m)*DD + t] * (float)m;
    H[node*DD + t] = v;
    split_bf16(v, Hhi[node*DD + t], Hlo[node*DD + t]);
}

// ---------------- state init: state[b,:] = mean over nodes of e --------------
__global__ void initstate_kernel(const float* __restrict__ H, float* __restrict__ state){
    int b = blockIdx.x, t = threadIdx.x;
    const float* p = H + (long)b*NN*DD + t;
    float s = 0.f;
    for(int i=0;i<NN;i++) s += p[(long)i*DD];
    state[b*DD + t] = s * (1.f/(float)NN);
}

// ---------------- fp32 SGEMM (kept for the tiny 64-row GEMMs) ----------------
__global__ void sgemm_kernel(const float* __restrict__ A, const float* __restrict__ W,
                             const float* __restrict__ bias, float* __restrict__ C){
    __shared__ float As[16][68];
    __shared__ float Bs[16][64];
    int tid = threadIdx.x;
    long bm = (long)blockIdx.y * 64;
    int  bn = blockIdx.x * 64;
    int ar = tid >> 2,  ac = (tid & 3)  * 4;
    int br = tid >> 4,  bc = (tid & 15) * 4;
    int tx = tid & 15,  ty = tid >> 4;
    float acc[4][4] = {};
    const float* Ap = A + (bm + ar)*256 + ac;
    const float* Wp = W + (long)br*256 + bn + bc;
    for(int k0 = 0; k0 < 256; k0 += 16){
        float4 av = *(const float4*)(Ap + k0);
        As[ac+0][ar] = av.x; As[ac+1][ar] = av.y;
        As[ac+2][ar] = av.z; As[ac+3][ar] = av.w;
        *(float4*)&Bs[br][bc] = *(const float4*)(Wp + (long)k0*256);
        __syncthreads();
#pragma unroll
        for(int kk = 0; kk < 16; kk++){
            float a[4], b[4];
#pragma unroll
            for(int i=0;i<4;i++) a[i] = As[kk][ty*4+i];
#pragma unroll
            for(int j=0;j<4;j++) b[j] = Bs[kk][tx*4+j];
#pragma unroll
            for(int i=0;i<4;i++)
#pragma unroll
                for(int j=0;j<4;j++) acc[i][j] += a[i]*b[j];
        }
        __syncthreads();
    }
#pragma unroll
    for(int i=0;i<4;i++){
        long row = bm + ty*4 + i;
        float4 o;
        o.x = acc[i][0] + bias[bn + tx*4 + 0];
        o.y = acc[i][1] + bias[bn + tx*4 + 1];
        o.z = acc[i][2] + bias[bn + tx*4 + 2];
        o.w = acc[i][3] + bias[bn + tx*4 + 3];
        *(float4*)(C + row*256 + bn + tx*4) = o;
    }
}

// ---------------- tensor-core bf16x3 GEMM: C[M,256]=A@W+b --------------------
// Block tile 64x256 (covers all N), K chunk 32, 8 warps of 32x64 warp tiles.
// Up to 3 (W, bias, C) sets selected by blockIdx.y (fused q/k/v etc.).
__device__ __forceinline__ void ldsm4(uint32_t* r, const void* p){
    uint32_t a = (uint32_t)__cvta_generic_to_shared(p);
    asm volatile("ldmatrix.sync.aligned.m8n8.x4.shared.b16 {%0,%1,%2,%3}, [%4];"
        : "=r"(r[0]),"=r"(r[1]),"=r"(r[2]),"=r"(r[3]) : "r"(a));
}
__device__ __forceinline__ void ldsm4t(uint32_t* r, const void* p){
    uint32_t a = (uint32_t)__cvta_generic_to_shared(p);
    asm volatile("ldmatrix.sync.aligned.m8n8.x4.trans.shared.b16 {%0,%1,%2,%3}, [%4];"
        : "=r"(r[0]),"=r"(r[1]),"=r"(r[2]),"=r"(r[3]) : "r"(a));
}
__device__ __forceinline__ void mma16816(float* c, const uint32_t* a, const uint32_t* b){
    asm volatile("mma.sync.aligned.m16n8k16.row.col.f32.bf16.bf16.f32 "
        "{%0,%1,%2,%3}, {%4,%5,%6,%7}, {%8,%9}, {%0,%1,%2,%3};"
        : "+f"(c[0]),"+f"(c[1]),"+f"(c[2]),"+f"(c[3])
        : "r"(a[0]),"r"(a[1]),"r"(a[2]),"r"(a[3]), "r"(b[0]),"r"(b[1]));
}

__global__ __launch_bounds__(256,1) void tcgemm3_kernel(
    const __nv_bfloat16* __restrict__ Ahi, const __nv_bfloat16* __restrict__ Alo,
    const __nv_bfloat16* __restrict__ Whi, const __nv_bfloat16* __restrict__ Wlo,
    const float* bias0, const float* bias1, const float* bias2,
    float* C0, float* C1, float* C2, int w0, int w1, int w2)
{
    __shared__ __nv_bfloat16 As[2][64][40];    // [hi/lo][m][k], row stride 80B
    __shared__ __nv_bfloat16 Bs[2][32][264];   // [hi/lo][k][n], row stride 528B
    int tid = threadIdx.x, lane = tid & 31, warp = tid >> 5;
    int sel = blockIdx.y;
    const float* bias = (sel==0) ? bias0 : ((sel==1) ? bias1 : bias2);
    float*       C    = (sel==0) ? C0    : ((sel==1) ? C1    : C2);
    int          wi   = (sel==0) ? w0    : ((sel==1) ? w1    : w2);
    const __nv_bfloat16* Bh = Whi + (long)wi * (DD*DD);
    const __nv_bfloat16* Bl = Wlo + (long)wi * (DD*DD);
    long bm = (long)blockIdx.x * 64;
    int wm = warp >> 2, wn = warp & 3;           // warp tile: rows wm*32.., cols wn*64..
    int am = tid >> 2, aseg = (tid & 3) * 8;     // A staging coords
    int bnn = lane * 8;                          // B staging n-offset (per thread)

    float c[2][8][4];
#pragma unroll
    for(int i=0;i<2;i++)
#pragma unroll
        for(int j=0;j<8;j++)
#pragma unroll
            for(int k=0;k<4;k++) c[i][j][k]=0.f;

    uint4 pa0, pa1, pbh[4], pbl[4];
#define LOADG(kt) { \
    pa0 = *(const uint4*)(Ahi + (bm+am)*256 + (kt)*32 + aseg); \
    pa1 = *(const uint4*)(Alo + (bm+am)*256 + (kt)*32 + aseg); \
    _Pragma("unroll") \
    for(int j=0;j<4;j++){ \
        long off = ((long)((kt)*32 + warp + 8*j))*256 + bnn; \
        pbh[j] = *(const uint4*)(Bh + off); \
        pbl[j] = *(const uint4*)(Bl + off); } }
#define STORES() { \
    *(uint4*)&As[0][am][aseg] = pa0; \
    *(uint4*)&As[1][am][aseg] = pa1; \
    _Pragma("unroll") \
    for(int j=0;j<4;j++){ \
        *(uint4*)&Bs[0][warp + 8*j][bnn] = pbh[j]; \
        *(uint4*)&Bs[1][warp + 8*j][bnn] = pbl[j]; } }

    LOADG(0); STORES(); __syncthreads();

    int q = lane >> 3, r = lane & 7;
    int arow = wm*32 + (q&1)*8 + r;   // + mt*16
    int acol = (q>>1)*8;              // + k16*16
    int bkrow = (q&1)*8 + r;          // + k16*16
    int bcol = wn*64 + (q>>1)*8;      // + p*16

    for(int kt = 0; kt < 8; kt++){
        if(kt < 7){ LOADG(kt+1); }
#pragma unroll
        for(int k16 = 0; k16 < 2; k16++){
            uint32_t ah[2][4], al[2][4];
#pragma unroll
            for(int mt=0; mt<2; mt++){
                ldsm4(ah[mt], &As[0][arow + mt*16][acol + k16*16]);
                ldsm4(al[mt], &As[1][arow + mt*16][acol + k16*16]);
            }
            uint32_t bh[8][2], bl[8][2];
#pragma unroll
            for(int p=0; p<4; p++){
                uint32_t t4[4];
                ldsm4t(t4, &Bs[0][bkrow + k16*16][bcol + p*16]);
                bh[2*p][0]=t4[0]; bh[2*p][1]=t4[1]; bh[2*p+1][0]=t4[2]; bh[2*p+1][1]=t4[3];
                ldsm4t(t4, &Bs[1][bkrow + k16*16][bcol + p*16]);
                bl[2*p][0]=t4[0]; bl[2*p][1]=t4[1]; bl[2*p+1][0]=t4[2]; bl[2*p+1][1]=t4[3];
            }
#pragma unroll
            for(int mt=0; mt<2; mt++)
#pragma unroll
                for(int nt=0; nt<8; nt++){
                    mma16816(c[mt][nt], ah[mt], bh[nt]);   // hi*hi
                    mma16816(c[mt][nt], ah[mt], bl[nt]);   // hi*lo
                    mma16816(c[mt][nt], al[mt], bh[nt]);   // lo*hi
                }
        }
        __syncthreads();
        if(kt < 7){ STORES(); __syncthreads(); }
    }

    int crow = wm*32 + (lane>>2);
    int ccol = wn*64 + (lane&3)*2;
#pragma unroll
    for(int mt=0; mt<2; mt++)
#pragma unroll
        for(int nt=0; nt<8; nt++){
            long row = bm + crow + mt*16;
            int col = ccol + nt*8;
            float b0v = bias[col], b1v = bias[col+1];
            float2 v0; v0.x = c[mt][nt][0] + b0v; v0.y = c[mt][nt][1] + b1v;
            *(float2*)&C[row*256 + col] = v0;
            float2 v1; v1.x = c[mt][nt][2] + b0v; v1.y = c[mt][nt][3] + b1v;
            *(float2*)&C[(row+8)*256 + col] = v1;
        }
#undef LOADG
#undef STORES
}

// ------------- step-1 attention: per node, 5 keys [cl,cr,h,e,s] --------------
__global__ void attn1_kernel(const float* __restrict__ Hq, const float* __restrict__ Hk,
                             const float* __restrict__ Hv,
                             const float* __restrict__ Ek, const float* __restrict__ Ev,
                             const float* __restrict__ Sk, const float* __restrict__ Sv,
                             const float* __restrict__ k1b, const float* __restrict__ v1b,
                             float* __restrict__ O,
                             __nv_bfloat16* __restrict__ Ohi, __nv_bfloat16* __restrict__ Olo){
    int  nb   = blockIdx.x;
    int  node = nb % NN;
    int  b    = nb / NN;
    int  t    = threadIdx.x;
    long base = (long)nb * DD;
    bool internal = node < 255;
    long lb = (long)(nb + node + 1) * DD;
    long rb = lb + DD;

    float qv = Hq[base + t];
    float s[5];
    s[0] = qv * (internal ? Hk[lb + t] : k1b[t]);
    s[1] = qv * (internal ? Hk[rb + t] : k1b[t]);
    s[2] = qv * Hk[base + t];
    s[3] = qv * Ek[base + t];
    s[4] = qv * Sk[b*DD + t];
#pragma unroll
    for(int o = 16; o; o >>= 1){
#pragma unroll
        for(int j=0;j<5;j++) s[j] += __shfl_xor_sync(0xffffffffu, s[j], o);
    }
    const float scale = 0.17677669529663687f;
    float mx = -1e30f;
#pragma unroll
    for(int j=0;j<5;j++){ s[j] *= scale; mx = fmaxf(mx, s[j]); }
    float w[5], sum = 0.f;
#pragma unroll
    for(int j=0;j<5;j++){ w[j] = __expf(s[j]-mx); sum += w[j]; }
    float inv = 1.f / sum;
    float v0 = internal ? Hv[lb + t] : v1b[t];
    float v1 = internal ? Hv[rb + t] : v1b[t];
    float v2 = Hv[base + t];
    float v3 = Ev[base + t];
    float v4 = Sv[b*DD + t];
    float ov = (w[0]*v0 + w[1]*v1 + w[2]*v2 + w[3]*v3 + w[4]*v4) * inv;
    O[base + t] = ov;
    split_bf16(ov, Ohi[base + t], Olo[base + t]);
}

// ------------- relu + layernorm (unbiased std, eps on std) -------------------
__global__ void relu_ln_kernel(const float* __restrict__ X, const float* __restrict__ gam,
                               const float* __restrict__ bet, float* __restrict__ Y,
                               __nv_bfloat16* __restrict__ Yhi, __nv_bfloat16* __restrict__ Ylo){
    long row = blockIdx.x;
    int  t   = threadIdx.x;
    __shared__ float wsh[8];
    __shared__ float stat[2];
    float x = fmaxf(X[row*DD + t], 0.f);

    float v = x;
#pragma unroll
    for(int o=16;o;o>>=1) v += __shfl_xor_sync(0xffffffffu, v, o);
    if((t&31)==0) wsh[t>>5] = v;
    __syncthreads();
    if(t < 32){
        float r = (t < 8) ? wsh[t] : 0.f;
#pragma unroll
        for(int o=4;o;o>>=1) r += __shfl_xor_sync(0xffffffffu, r, o);
        if(t==0) stat[0] = r;
    }
    __syncthreads();
    float mean = stat[0] * (1.f/256.f);
    float dx = x - mean;

    v = dx*dx;
#pragma unroll
    for(int o=16;o;o>>=1) v += __shfl_xor_sync(0xffffffffu, v, o);
    if((t&31)==0) wsh[t>>5] = v;
    __syncthreads();
    if(t < 32){
        float r = (t < 8) ? wsh[t] : 0.f;
#pragma unroll
        for(int o=4;o;o>>=1) r += __shfl_xor_sync(0xffffffffu, r, o);
        if(t==0) stat[1] = r;
    }
    __syncthreads();
    float sd = sqrtf(stat[1] * (1.f/255.f));
    float y = gam[t] * dx / (sd + 1e-6f) + bet[t];
    Y[row*DD + t] = y;
    if(Yhi){ split_bf16(y, Yhi[row*DD + t], Ylo[row*DD + t]); }
}

// ------------- step-2 attention: state attends over 511 h rows ---------------
__global__ void attn2_kernel(const float* __restrict__ Q2, const float* __restrict__ K2,
                             const float* __restrict__ V2, float* __restrict__ O2){
    int b = blockIdx.x >> 3, head = blockIdx.x & 7;
    int t = threadIdx.x;
    __shared__ float sc[NN];
    __shared__ float qs[32];
    __shared__ float red[8][33];
    __shared__ float wsh[8];
    __shared__ float stat[2];
    if(t < 32) qs[t] = Q2[b*DD + head*32 + t];
    __syncthreads();

    const float scale = 0.17677669529663687f;
    float lm = -1e30f;
    for(int i = t; i < NN; i += 256){
        const float* kp = K2 + ((long)(b*NN + i))*DD + head*32;
        float d = 0.f;
#pragma unroll
        for(int j=0;j<32;j++) d += qs[j]*kp[j];
        d *= scale;
        sc[i] = d;
        lm = fmaxf(lm, d);
    }
#pragma unroll
    for(int o=16;o;o>>=1) lm = fmaxf(lm, __shfl_xor_sync(0xffffffffu, lm, o));
    if((t&31)==0) wsh[t>>5] = lm;
    __syncthreads();
    if(t < 32){
        float r = (t < 8) ? wsh[t] : -1e30f;
#pragma unroll
        for(int o=4;o;o>>=1) r = fmaxf(r, __shfl_xor_sync(0xffffffffu, r, o));
        if(t==0) stat[0] = r;
    }
    __syncthreads();
    float mx = stat[0];
    float ls = 0.f;
    for(int i = t; i < NN; i += 256){ float w = __expf(sc[i]-mx); sc[i] = w; ls += w; }
#pragma unroll
    for(int o=16;o;o>>=1) ls += __shfl_xor_sync(0xffffffffu, ls, o);
    if((t&31)==0) wsh[t>>5] = ls;
    __syncthreads();
    if(t < 32){
        float r = (t < 8) ? wsh[t] : 0.f;
#pragma unroll
        for(int o=4;o;o>>=1) r += __shfl_xor_sync(0xffffffffu, r, o);
        if(t==0) stat[1] = r;
    }
    __syncthreads();
    float inv = 1.f / stat[1];

    int g = t >> 5, lane = t & 31;
    float acc = 0.f;
    for(int i = g; i < NN; i += 8)
        acc += sc[i] * V2[((long)(b*NN + i))*DD + head*32 + lane];
    red[g][lane] = acc;
    __syncthreads();
    if(t < 32){
        float s2 = 0.f;
#pragma unroll
        for(int gg=0; gg<8; gg++) s2 += red[gg][t];
        O2[b*DD + head*32 + t] = s2 * inv;
    }
}

// ------------- final: logits = H @ linw[256,5] + linb ------------------------
__global__ void logits_kernel(const float* __restrict__ H, const float* __restrict__ linw,
                              const float* __restrict__ linb, float* __restrict__ out){
    __shared__ float w[DD*5];
    int t = threadIdx.x;
    for(int i = t; i < DD*5; i += 256) w[i] = linw[i];
    __syncthreads();
    int warp = t >> 5, lane = t & 31;
    long row = (long)blockIdx.x*8 + warp;
    const float* hp = H + row*DD;
    float hr[8];
#pragma unroll
    for(int k=0;k<8;k++) hr[k] = hp[lane + 32*k];
#pragma unroll
    for(int c=0;c<5;c++){
        float a = 0.f;
#pragma unroll
        for(int k=0;k<8;k++) a += hr[k] * w[(lane+32*k)*5 + c];
#pragma unroll
        for(int o=16;o;o>>=1) a += __shfl_xor_sync(0xffffffffu, a, o);
        if(lane==0) out[row*5 + c] = a + linb[c];
    }
}

// ------------------------------- host side -----------------------------------
extern "C" void kernel_launch(void* const* d_in, const int* in_sizes, int n_in,
                              void* d_out, int out_size){
    const int*   wordid = (const int*)  d_in[0];
    const int*   mask   = (const int*)  d_in[1];
    const float* emb    = (const float*)d_in[2];
    const float* q1w=(const float*)d_in[3],  *q1b=(const float*)d_in[4];
    const float* k1w=(const float*)d_in[5],  *k1b=(const float*)d_in[6];
    const float* v1w=(const float*)d_in[7],  *v1b=(const float*)d_in[8];
    const float* o1w=(const float*)d_in[9],  *o1b=(const float*)d_in[10];
    const float* q2w=(const float*)d_in[11], *q2b=(const float*)d_in[12];
    const float* k2w=(const float*)d_in[13], *k2b=(const float*)d_in[14];
    const float* v2w=(const float*)d_in[15], *v2b=(const float*)d_in[16];
    const float* o2w=(const float*)d_in[17], *o2b=(const float*)d_in[18];
    const float* ln1g=(const float*)d_in[19],*ln1bb=(const float*)d_in[20];
    const float* ln2g=(const float*)d_in[21],*ln2bb=(const float*)d_in[22];
    const float* linw=(const float*)d_in[23],*linb=(const float*)d_in[24];
    float* out = (float*)d_out;

    float *H,*Ek,*Ev,*Hq,*Hk,*Hv,*O,*state,*Sk,*Sv,*q2,*o2;
    __nv_bfloat16 *Hhi,*Hlo,*Ohi,*Olo,*Whi,*Wlo;
    cudaGetSymbolAddress((void**)&H,  g_H);
    cudaGetSymbolAddress((void**)&Ek, g_Ek);
    cudaGetSymbolAddress((void**)&Ev, g_Ev);
    cudaGetSymbolAddress((void**)&Hq, g_Hq);
    cudaGetSymbolAddress((void**)&Hk, g_Hk);
    cudaGetSymbolAddress((void**)&Hv, g_Hv);
    cudaGetSymbolAddress((void**)&O,  g_O);
    cudaGetSymbolAddress((void**)&state, g_state);
    cudaGetSymbolAddress((void**)&Sk, g_Sk);
    cudaGetSymbolAddress((void**)&Sv, g_Sv);
    cudaGetSymbolAddress((void**)&q2, g_q2);
    cudaGetSymbolAddress((void**)&o2, g_o2);
    cudaGetSymbolAddress((void**)&Hhi, g_Hhi);
    cudaGetSymbolAddress((void**)&Hlo, g_Hlo);
    cudaGetSymbolAddress((void**)&Ohi, g_Ohi);
    cudaGetSymbolAddress((void**)&Olo, g_Olo);
    cudaGetSymbolAddress((void**)&Whi, g_Whi);
    cudaGetSymbolAddress((void**)&Wlo, g_Wlo);

    // weight splits: order [q1w,k1w,v1w,o1w,k2w,v2w]
    const float* ws[6] = {q1w, k1w, v1w, o1w, k2w, v2w};
    for(int i=0;i<6;i++)
        wsplit_kernel<<<DD*DD/256, 256>>>(ws[i], Whi + (long)i*DD*DD, Wlo + (long)i*DD*DD);

    dim3 gSm(4, 1);

    embed_kernel    <<<MR, 256>>>(wordid, mask, emb, H, Hhi, Hlo);
    initstate_kernel<<<BB, 256>>>(H, state);
    // e-slot K/V projections (once): Ek = e@k1w+k1b, Ev = e@v1w+v1b
    tcgemm3_kernel<<<dim3(MR/64, 2), 256>>>(Hhi, Hlo, Whi, Wlo,
                                            k1b, v1b, v1b, Ek, Ev, Ev, 1, 2, 2);

    for(int it = 0; it < 5; it++){
        // step 1: q/k/v projections fused in one launch
        tcgemm3_kernel<<<dim3(MR/64, 3), 256>>>(Hhi, Hlo, Whi, Wlo,
                                                q1b, k1b, v1b, Hq, Hk, Hv, 0, 1, 2);
        sgemm_kernel<<<gSm, 256>>>(state, k1w, k1b, Sk);
        sgemm_kernel<<<gSm, 256>>>(state, v1w, v1b, Sv);
        attn1_kernel<<<MR, 256>>>(Hq, Hk, Hv, Ek, Ev, Sk, Sv, k1b, v1b, O, Ohi, Olo);
        tcgemm3_kernel<<<dim3(MR/64, 1), 256>>>(Ohi, Olo, Whi, Wlo,
                                                o1b, o1b, o1b, Hq, Hq, Hq, 3, 3, 3);
        relu_ln_kernel<<<MR, 256>>>(Hq, ln1g, ln1bb, H, Hhi, Hlo);

        // step 2: state attends over h
        tcgemm3_kernel<<<dim3(MR/64, 2), 256>>>(Hhi, Hlo, Whi, Wlo,
                                                k2b, v2b, v2b, Hk, Hv, Hv, 4, 5, 5);
        sgemm_kernel<<<gSm, 256>>>(state, q2w, q2b, q2);
        attn2_kernel<<<BB*8, 256>>>(q2, Hk, Hv, o2);
        sgemm_kernel<<<gSm, 256>>>(o2, o2w, o2b, q2);
        relu_ln_kernel<<<BB, 256>>>(q2, ln2g, ln2bb, state, (__nv_bfloat16*)0, (__nv_bfloat16*)0);
    }

    logits_kernel<<<MR/8, 256>>>(H, linw, linb, out);
}

// round 6
// speedup vs baseline: 2.0258x; 1.1421x over previous
#include <cuda_runtime.h>
#include <cuda_bf16.h>
#include <stdint.h>

// Problem constants
#define BB 64
#define NN 511
#define DD 256
#define MR (BB*NN)   // 32704 rows

// ---------------- scratch (device globals; no allocation allowed) -------------
__device__ float g_H [MR*DD];
__device__ float g_Ek[MR*DD];
__device__ float g_Ev[MR*DD];
__device__ float g_Hq[MR*DD];
__device__ float g_Hk[MR*DD];
__device__ float g_Hv[MR*DD];
__device__ float g_state[BB*DD];
__device__ float g_Sk[BB*DD];
__device__ float g_Sv[BB*DD];
__device__ float g_q2[BB*DD];
__device__ float g_o2[BB*DD];
__device__ float g_sc[BB*8*NN];     // step-2 scores
__device__ float g_qt[BB*8*DD];     // step-2 folded queries
__device__ float g_hbar[BB*8*DD];   // step-2 mixed h per head
__device__ float g_k2t[DD*DD];      // k2w transposed
// bf16 split operands for tensor-core GEMMs
__device__ __nv_bfloat16 g_Hhi[MR*DD];
__device__ __nv_bfloat16 g_Hlo[MR*DD];
__device__ __nv_bfloat16 g_Ohi[MR*DD];
__device__ __nv_bfloat16 g_Olo[MR*DD];
__device__ __nv_bfloat16 g_Whi[4*DD*DD];   // [q1,k1,v1,o1]
__device__ __nv_bfloat16 g_Wlo[4*DD*DD];

__device__ __forceinline__ void split_bf16(float x, __nv_bfloat16& h, __nv_bfloat16& l){
    h = __float2bfloat16_rn(x);
    l = __float2bfloat16_rn(x - __bfloat162float(h));
}

// ---------------- weight split (4 weights in one launch) ---------------------
__global__ void wsplit_kernel(const float* W0, const float* W1, const float* W2,
                              const float* W3,
                              __nv_bfloat16* __restrict__ hi, __nv_bfloat16* __restrict__ lo){
    int w = blockIdx.y;
    const float* W = (w==0)?W0:((w==1)?W1:((w==2)?W2:W3));
    int i = blockIdx.x*256 + threadIdx.x;
    long o = (long)w*DD*DD + i;
    split_bf16(W[i], hi[o], lo[o]);
}

// ---------------- fp32 transpose (k2w) ---------------------------------------
__global__ void trans_kernel(const float* __restrict__ W, float* __restrict__ Wt){
    __shared__ float t[32][33];
    int bx = blockIdx.x*32, by = blockIdx.y*32;
    int x = threadIdx.x & 31, y0 = threadIdx.x >> 5;
#pragma unroll
    for(int i=0;i<4;i++){ int y=y0*4+i; t[y][x] = W[(by+y)*256 + bx + x]; }
    __syncthreads();
#pragma unroll
    for(int i=0;i<4;i++){ int y=y0*4+i; Wt[(long)(bx+y)*256 + by + x] = t[x][y]; }
}

// ---------------- embedding ---------------------------------------------------
__global__ void embed_kernel(const int* __restrict__ wordid, const int* __restrict__ mask,
                             const float* __restrict__ emb, float* __restrict__ H,
                             __nv_bfloat16* __restrict__ Hhi, __nv_bfloat16* __restrict__ Hlo){
    long node = blockIdx.x;
    int  t    = threadIdx.x;
    int wid = wordid[node];
    int m   = mask[node];
    float v = emb[(long)(wid*m)*DD + t] * (float)m;
    H[node*DD + t] = v;
    split_bf16(v, Hhi[node*DD + t], Hlo[node*DD + t]);
}

// ---------------- state init --------------------------------------------------
__global__ void initstate_kernel(const float* __restrict__ H, float* __restrict__ state){
    int b = blockIdx.x, t = threadIdx.x;
    const float* p = H + (long)b*NN*DD + t;
    float s = 0.f;
    for(int i=0;i<NN;i++) s += p[(long)i*DD];
    state[b*DD + t] = s * (1.f/(float)NN);
}

// ---------------- tensor-core bf16x3 GEMM (verified round-2 kernel) ----------
__device__ __forceinline__ void ldsm4(uint32_t* r, const void* p){
    uint32_t a = (uint32_t)__cvta_generic_to_shared(p);
    asm volatile("ldmatrix.sync.aligned.m8n8.x4.shared.b16 {%0,%1,%2,%3}, [%4];"
        : "=r"(r[0]),"=r"(r[1]),"=r"(r[2]),"=r"(r[3]) : "r"(a));
}
__device__ __forceinline__ void ldsm4t(uint32_t* r, const void* p){
    uint32_t a = (uint32_t)__cvta_generic_to_shared(p);
    asm volatile("ldmatrix.sync.aligned.m8n8.x4.trans.shared.b16 {%0,%1,%2,%3}, [%4];"
        : "=r"(r[0]),"=r"(r[1]),"=r"(r[2]),"=r"(r[3]) : "r"(a));
}
__device__ __forceinline__ void mma16816(float* c, const uint32_t* a, const uint32_t* b){
    asm volatile("mma.sync.aligned.m16n8k16.row.col.f32.bf16.bf16.f32 "
        "{%0,%1,%2,%3}, {%4,%5,%6,%7}, {%8,%9}, {%0,%1,%2,%3};"
        : "+f"(c[0]),"+f"(c[1]),"+f"(c[2]),"+f"(c[3])
        : "r"(a[0]),"r"(a[1]),"r"(a[2]),"r"(a[3]), "r"(b[0]),"r"(b[1]));
}

__global__ __launch_bounds__(256,1) void tcgemm3_kernel(
    const __nv_bfloat16* __restrict__ Ahi, const __nv_bfloat16* __restrict__ Alo,
    const __nv_bfloat16* __restrict__ Whi, const __nv_bfloat16* __restrict__ Wlo,
    const float* bias0, const float* bias1, const float* bias2,
    float* C0, float* C1, float* C2, int w0, int w1, int w2)
{
    __shared__ __nv_bfloat16 As[2][64][40];
    __shared__ __nv_bfloat16 Bs[2][32][264];
    int tid = threadIdx.x, lane = tid & 31, warp = tid >> 5;
    int sel = blockIdx.y;
    const float* bias = (sel==0) ? bias0 : ((sel==1) ? bias1 : bias2);
    float*       C    = (sel==0) ? C0    : ((sel==1) ? C1    : C2);
    int          wi   = (sel==0) ? w0    : ((sel==1) ? w1    : w2);
    const __nv_bfloat16* Bh = Whi + (long)wi * (DD*DD);
    const __nv_bfloat16* Bl = Wlo + (long)wi * (DD*DD);
    long bm = (long)blockIdx.x * 64;
    int wm = warp >> 2, wn = warp & 3;
    int am = tid >> 2, aseg = (tid & 3) * 8;
    int bnn = lane * 8;

    float c[2][8][4];
#pragma unroll
    for(int i=0;i<2;i++)
#pragma unroll
        for(int j=0;j<8;j++)
#pragma unroll
            for(int k=0;k<4;k++) c[i][j][k]=0.f;

    uint4 pa0, pa1, pbh[4], pbl[4];
#define LOADG(kt) { \
    pa0 = *(const uint4*)(Ahi + (bm+am)*256 + (kt)*32 + aseg); \
    pa1 = *(const uint4*)(Alo + (bm+am)*256 + (kt)*32 + aseg); \
    _Pragma("unroll") \
    for(int j=0;j<4;j++){ \
        long off = ((long)((kt)*32 + warp + 8*j))*256 + bnn; \
        pbh[j] = *(const uint4*)(Bh + off); \
        pbl[j] = *(const uint4*)(Bl + off); } }
#define STORES() { \
    *(uint4*)&As[0][am][aseg] = pa0; \
    *(uint4*)&As[1][am][aseg] = pa1; \
    _Pragma("unroll") \
    for(int j=0;j<4;j++){ \
        *(uint4*)&Bs[0][warp + 8*j][bnn] = pbh[j]; \
        *(uint4*)&Bs[1][warp + 8*j][bnn] = pbl[j]; } }

    LOADG(0); STORES(); __syncthreads();

    int q = lane >> 3, r = lane & 7;
    int arow = wm*32 + (q&1)*8 + r;
    int acol = (q>>1)*8;
    int bkrow = (q&1)*8 + r;
    int bcol = wn*64 + (q>>1)*8;

    for(int kt = 0; kt < 8; kt++){
        if(kt < 7){ LOADG(kt+1); }
#pragma unroll
        for(int k16 = 0; k16 < 2; k16++){
            uint32_t ah[2][4], al[2][4];
#pragma unroll
            for(int mt=0; mt<2; mt++){
                ldsm4(ah[mt], &As[0][arow + mt*16][acol + k16*16]);
                ldsm4(al[mt], &As[1][arow + mt*16][acol + k16*16]);
            }
            uint32_t bh[8][2], bl[8][2];
#pragma unroll
            for(int p=0; p<4; p++){
                uint32_t t4[4];
                ldsm4t(t4, &Bs[0][bkrow + k16*16][bcol + p*16]);
                bh[2*p][0]=t4[0]; bh[2*p][1]=t4[1]; bh[2*p+1][0]=t4[2]; bh[2*p+1][1]=t4[3];
                ldsm4t(t4, &Bs[1][bkrow + k16*16][bcol + p*16]);
                bl[2*p][0]=t4[0]; bl[2*p][1]=t4[1]; bl[2*p+1][0]=t4[2]; bl[2*p+1][1]=t4[3];
            }
#pragma unroll
            for(int mt=0; mt<2; mt++)
#pragma unroll
                for(int nt=0; nt<8; nt++){
                    mma16816(c[mt][nt], ah[mt], bh[nt]);
                    mma16816(c[mt][nt], ah[mt], bl[nt]);
                    mma16816(c[mt][nt], al[mt], bh[nt]);
                }
        }
        __syncthreads();
        if(kt < 7){ STORES(); __syncthreads(); }
    }

    int crow = wm*32 + (lane>>2);
    int ccol = wn*64 + (lane&3)*2;
#pragma unroll
    for(int mt=0; mt<2; mt++)
#pragma unroll
        for(int nt=0; nt<8; nt++){
            long row = bm + crow + mt*16;
            int col = ccol + nt*8;
            float b0v = bias[col], b1v = bias[col+1];
            float2 v0; v0.x = c[mt][nt][0] + b0v; v0.y = c[mt][nt][1] + b1v;
            *(float2*)&C[row*256 + col] = v0;
            float2 v1; v1.x = c[mt][nt][2] + b0v; v1.y = c[mt][nt][3] + b1v;
            *(float2*)&C[(row+8)*256 + col] = v1;
        }
#undef LOADG
#undef STORES
}

// ------- fp32 SGEMM for the tiny 64-row state GEMMs (up to 2 outputs) --------
__global__ void sgemm_kernel(const float* __restrict__ A, const float* __restrict__ W0,
                             const float* __restrict__ b0v, float* __restrict__ C0v,
                             const float* __restrict__ W1, const float* __restrict__ b1v,
                             float* __restrict__ C1v){
    __shared__ float As[16][68];
    __shared__ float Bs[16][64];
    int tid = threadIdx.x;
    const float* W    = blockIdx.y ? W1  : W0;
    const float* bias = blockIdx.y ? b1v : b0v;
    float*       C    = blockIdx.y ? C1v : C0v;
    int  bn = blockIdx.x * 64;
    int ar = tid >> 2,  ac = (tid & 3)  * 4;
    int br = tid >> 4,  bc = (tid & 15) * 4;
    int tx = tid & 15,  ty = tid >> 4;
    float acc[4][4] = {};
    const float* Ap = A + ar*256 + ac;
    const float* Wp = W + (long)br*256 + bn + bc;
    for(int k0 = 0; k0 < 256; k0 += 16){
        float4 av = *(const float4*)(Ap + k0);
        As[ac+0][ar] = av.x; As[ac+1][ar] = av.y;
        As[ac+2][ar] = av.z; As[ac+3][ar] = av.w;
        *(float4*)&Bs[br][bc] = *(const float4*)(Wp + (long)k0*256);
        __syncthreads();
#pragma unroll
        for(int kk = 0; kk < 16; kk++){
            float a[4], b[4];
#pragma unroll
            for(int i=0;i<4;i++) a[i] = As[kk][ty*4+i];
#pragma unroll
            for(int j=0;j<4;j++) b[j] = Bs[kk][tx*4+j];
#pragma unroll
            for(int i=0;i<4;i++)
#pragma unroll
                for(int j=0;j<4;j++) acc[i][j] += a[i]*b[j];
        }
        __syncthreads();
    }
#pragma unroll
    for(int i=0;i<4;i++){
        long row = ty*4 + i;
        float4 o;
        o.x = acc[i][0] + bias[bn + tx*4 + 0];
        o.y = acc[i][1] + bias[bn + tx*4 + 1];
        o.z = acc[i][2] + bias[bn + tx*4 + 2];
        o.w = acc[i][3] + bias[bn + tx*4 + 3];
        *(float4*)(C + row*256 + bn + tx*4) = o;
    }
}

// ------------- step-1 attention: per node, 5 keys [cl,cr,h,e,s] --------------
__global__ void attn1_kernel(const float* __restrict__ Hq, const float* __restrict__ Hk,
                             const float* __restrict__ Hv,
                             const float* __restrict__ Ek, const float* __restrict__ Ev,
                             const float* __restrict__ Sk, const float* __restrict__ Sv,
                             const float* __restrict__ k1b, const float* __restrict__ v1b,
                             __nv_bfloat16* __restrict__ Ohi, __nv_bfloat16* __restrict__ Olo){
    int  nb   = blockIdx.x;
    int  node = nb % NN;
    int  b    = nb / NN;
    int  t    = threadIdx.x;
    long base = (long)nb * DD;
    bool internal = node < 255;
    long lb = (long)(nb + node + 1) * DD;
    long rb = lb + DD;

    float qv = Hq[base + t];
    float s[5];
    s[0] = qv * (internal ? Hk[lb + t] : k1b[t]);
    s[1] = qv * (internal ? Hk[rb + t] : k1b[t]);
    s[2] = qv * Hk[base + t];
    s[3] = qv * Ek[base + t];
    s[4] = qv * Sk[b*DD + t];
#pragma unroll
    for(int o = 16; o; o >>= 1){
#pragma unroll
        for(int j=0;j<5;j++) s[j] += __shfl_xor_sync(0xffffffffu, s[j], o);
    }
    const float scale = 0.17677669529663687f;
    float mx = -1e30f;
#pragma unroll
    for(int j=0;j<5;j++){ s[j] *= scale; mx = fmaxf(mx, s[j]); }
    float w[5], sum = 0.f;
#pragma unroll
    for(int j=0;j<5;j++){ w[j] = __expf(s[j]-mx); sum += w[j]; }
    float inv = 1.f / sum;
    float v0 = internal ? Hv[lb + t] : v1b[t];
    float v1 = internal ? Hv[rb + t] : v1b[t];
    float v2 = Hv[base + t];
    float v3 = Ev[base + t];
    float v4 = Sv[b*DD + t];
    float ov = (w[0]*v0 + w[1]*v1 + w[2]*v2 + w[3]*v3 + w[4]*v4) * inv;
    split_bf16(ov, Ohi[base + t], Olo[base + t]);
}

// ------------- relu + layernorm (unbiased std, eps on std) -------------------
__global__ void relu_ln_kernel(const float* __restrict__ X, const float* __restrict__ gam,
                               const float* __restrict__ bet, float* __restrict__ Y,
                               __nv_bfloat16* __restrict__ Yhi, __nv_bfloat16* __restrict__ Ylo){
    long row = blockIdx.x;
    int  t   = threadIdx.x;
    __shared__ float wsh[8];
    __shared__ float stat[2];
    float x = fmaxf(X[row*DD + t], 0.f);

    float v = x;
#pragma unroll
    for(int o=16;o;o>>=1) v += __shfl_xor_sync(0xffffffffu, v, o);
    if((t&31)==0) wsh[t>>5] = v;
    __syncthreads();
    if(t < 32){
        float r = (t < 8) ? wsh[t] : 0.f;
#pragma unroll
        for(int o=4;o;o>>=1) r += __shfl_xor_sync(0xffffffffu, r, o);
        if(t==0) stat[0] = r;
    }
    __syncthreads();
    float mean = stat[0] * (1.f/256.f);
    float dx = x - mean;

    v = dx*dx;
#pragma unroll
    for(int o=16;o;o>>=1) v += __shfl_xor_sync(0xffffffffu, v, o);
    if((t&31)==0) wsh[t>>5] = v;
    __syncthreads();
    if(t < 32){
        float r = (t < 8) ? wsh[t] : 0.f;
#pragma unroll
        for(int o=4;o;o>>=1) r += __shfl_xor_sync(0xffffffffu, r, o);
        if(t==0) stat[1] = r;
    }
    __syncthreads();
    float sd = sqrtf(stat[1] * (1.f/255.f));
    float y = gam[t] * dx / (sd + 1e-6f) + bet[t];
    Y[row*DD + t] = y;
    if(Yhi){ split_bf16(y, Yhi[row*DD + t], Ylo[row*DD + t]); }
}

// ============= step 2 (algebraic): no big GEMMs ===============================
// qt[b,h,k] = sum_d k2w[k, h*32+d] * q2[b, h*32+d]   (k2b dropped: uniform shift)
__global__ void qt_kernel(const float* __restrict__ k2t, const float* __restrict__ q2,
                          float* __restrict__ qt){
    int b = blockIdx.x, hh = blockIdx.y, k = threadIdx.x;
    __shared__ float q2s[32];
    if(k < 32) q2s[k] = q2[b*DD + hh*32 + k];
    __syncthreads();
    float a = 0.f;
#pragma unroll
    for(int d = 0; d < 32; d++) a += k2t[(long)(hh*32+d)*256 + k] * q2s[d];
    qt[((long)b*8 + hh)*DD + k] = a;
}

// sc[b,h,i] = scale * dot(H[b,i,:], qt[b,h,:])
__global__ void sc_kernel(const float* __restrict__ H, const float* __restrict__ qt,
                          float* __restrict__ sc){
    int b = blockIdx.y, rb = blockIdx.x;
    int t = threadIdx.x, warp = t >> 5, lane = t & 31;
    __shared__ float qts[8][256];
    for(int i = t; i < 8*256; i += 256) qts[i>>8][i&255] = qt[((long)b*8 + (i>>8))*DD + (i&255)];
    __syncthreads();
    const float scale = 0.17677669529663687f;
#pragma unroll
    for(int r = 0; r < 8; r++){
        int i = rb*64 + r*8 + warp;
        if(i < NN){
            const float* hp = H + ((long)b*NN + i)*DD;
            float hv[8];
#pragma unroll
            for(int j=0;j<8;j++) hv[j] = hp[lane + 32*j];
#pragma unroll
            for(int hh=0; hh<8; hh++){
                float s = 0.f;
#pragma unroll
                for(int j=0;j<8;j++) s += hv[j]*qts[hh][lane + 32*j];
#pragma unroll
                for(int o=16;o;o>>=1) s += __shfl_xor_sync(0xffffffffu, s, o);
                if(lane == 0) sc[((long)b*8 + hh)*NN + i] = s * scale;
            }
        }
    }
}

// softmax per (b,h) + hbar[b,h,:] = sum_i a_i H[b,i,:]
__global__ void mix_kernel(const float* __restrict__ H, const float* __restrict__ sc,
                           float* __restrict__ hbar){
    int b = blockIdx.x, t = threadIdx.x, warp = t >> 5, lane = t & 31;
    __shared__ float wsm[8][NN];
    {
        const float* sp = sc + ((long)b*8 + warp)*NN;
        float mx = -1e30f;
        for(int i = lane; i < NN; i += 32) mx = fmaxf(mx, sp[i]);
#pragma unroll
        for(int o=16;o;o>>=1) mx = fmaxf(mx, __shfl_xor_sync(0xffffffffu, mx, o));
        float sum = 0.f;
        for(int i = lane; i < NN; i += 32){ float w = __expf(sp[i]-mx); wsm[warp][i] = w; sum += w; }
#pragma unroll
        for(int o=16;o;o>>=1) sum += __shfl_xor_sync(0xffffffffu, sum, o);
        float inv = 1.f/sum;
        for(int i = lane; i < NN; i += 32) wsm[warp][i] *= inv;
    }
    __syncthreads();
    float acc[8] = {};
    const float* hp = H + (long)b*NN*DD + t;
    for(int i = 0; i < NN; i++){
        float hval = hp[(long)i*DD];
        float w0=wsm[0][i], w1=wsm[1][i], w2=wsm[2][i], w3=wsm[3][i];
        float w4=wsm[4][i], w5=wsm[5][i], w6=wsm[6][i], w7=wsm[7][i];
        acc[0]+=w0*hval; acc[1]+=w1*hval; acc[2]+=w2*hval; acc[3]+=w3*hval;
        acc[4]+=w4*hval; acc[5]+=w5*hval; acc[6]+=w6*hval; acc[7]+=w7*hval;
    }
#pragma unroll
    for(int hh=0; hh<8; hh++) hbar[((long)b*8 + hh)*DD + t] = acc[hh];
}

// o2[b, h*32+d] = dot(hbar[b,h,:], v2w[:, h*32+d]) + v2b
__global__ void vproj_kernel(const float* __restrict__ hbar, const float* __restrict__ v2w,
                             const float* __restrict__ v2b, float* __restrict__ o2){
    int b = blockIdx.x, t = threadIdx.x;
    __shared__ float hb[8][256];
    for(int i = t; i < 8*256; i += 256) hb[i>>8][i&255] = hbar[((long)b*8 + (i>>8))*DD + (i&255)];
    __syncthreads();
    int hh = t >> 5;
    float a = 0.f;
    for(int k = 0; k < 256; k++) a += hb[hh][k] * v2w[(long)k*256 + t];
    o2[b*DD + t] = a + v2b[t];
}

// ------------- final: logits = H @ linw[256,5] + linb ------------------------
__global__ void logits_kernel(const float* __restrict__ H, const float* __restrict__ linw,
                              const float* __restrict__ linb, float* __restrict__ out){
    __shared__ float w[DD*5];
    int t = threadIdx.x;
    for(int i = t; i < DD*5; i += 256) w[i] = linw[i];
    __syncthreads();
    int warp = t >> 5, lane = t & 31;
    long row = (long)blockIdx.x*8 + warp;
    const float* hp = H + row*DD;
    float hr[8];
#pragma unroll
    for(int k=0;k<8;k++) hr[k] = hp[lane + 32*k];
#pragma unroll
    for(int c=0;c<5;c++){
        float a = 0.f;
#pragma unroll
        for(int k=0;k<8;k++) a += hr[k] * w[(lane+32*k)*5 + c];
#pragma unroll
        for(int o=16;o;o>>=1) a += __shfl_xor_sync(0xffffffffu, a, o);
        if(lane==0) out[row*5 + c] = a + linb[c];
    }
}

// ------------------------------- host side -----------------------------------
extern "C" void kernel_launch(void* const* d_in, const int* in_sizes, int n_in,
                              void* d_out, int out_size){
    const int*   wordid = (const int*)  d_in[0];
    const int*   mask   = (const int*)  d_in[1];
    const float* emb    = (const float*)d_in[2];
    const float* q1w=(const float*)d_in[3],  *q1b=(const float*)d_in[4];
    const float* k1w=(const float*)d_in[5],  *k1b=(const float*)d_in[6];
    const float* v1w=(const float*)d_in[7],  *v1b=(const float*)d_in[8];
    const float* o1w=(const float*)d_in[9],  *o1b=(const float*)d_in[10];
    const float* q2w=(const float*)d_in[11], *q2b=(const float*)d_in[12];
    const float* k2w=(const float*)d_in[13], *k2b=(const float*)d_in[14];
    const float* v2w=(const float*)d_in[15], *v2b=(const float*)d_in[16];
    const float* o2w=(const float*)d_in[17], *o2b=(const float*)d_in[18];
    const float* ln1g=(const float*)d_in[19],*ln1bb=(const float*)d_in[20];
    const float* ln2g=(const float*)d_in[21],*ln2bb=(const float*)d_in[22];
    const float* linw=(const float*)d_in[23],*linb=(const float*)d_in[24];
    float* out = (float*)d_out;
    (void)k2b;  // uniform score shift -> softmax invariant

    float *H,*Ek,*Ev,*Hq,*Hk,*Hv,*state,*Sk,*Sv,*q2,*o2,*sc,*qt,*hbar,*k2t;
    __nv_bfloat16 *Hhi,*Hlo,*Ohi,*Olo,*Whi,*Wlo;
    cudaGetSymbolAddress((void**)&H,  g_H);
    cudaGetSymbolAddress((void**)&Ek, g_Ek);
    cudaGetSymbolAddress((void**)&Ev, g_Ev);
    cudaGetSymbolAddress((void**)&Hq, g_Hq);
    cudaGetSymbolAddress((void**)&Hk, g_Hk);
    cudaGetSymbolAddress((void**)&Hv, g_Hv);
    cudaGetSymbolAddress((void**)&state, g_state);
    cudaGetSymbolAddress((void**)&Sk, g_Sk);
    cudaGetSymbolAddress((void**)&Sv, g_Sv);
    cudaGetSymbolAddress((void**)&q2, g_q2);
    cudaGetSymbolAddress((void**)&o2, g_o2);
    cudaGetSymbolAddress((void**)&sc, g_sc);
    cudaGetSymbolAddress((void**)&qt, g_qt);
    cudaGetSymbolAddress((void**)&hbar, g_hbar);
    cudaGetSymbolAddress((void**)&k2t, g_k2t);
    cudaGetSymbolAddress((void**)&Hhi, g_Hhi);
    cudaGetSymbolAddress((void**)&Hlo, g_Hlo);
    cudaGetSymbolAddress((void**)&Ohi, g_Ohi);
    cudaGetSymbolAddress((void**)&Olo, g_Olo);
    cudaGetSymbolAddress((void**)&Whi, g_Whi);
    cudaGetSymbolAddress((void**)&Wlo, g_Wlo);

    int mt = MR/64;  // 511

    // launch order chosen so ncu -s 5 profiles the fused qkv tcgemm3 (launch #5)
    wsplit_kernel<<<dim3(DD*DD/256, 4), 256>>>(q1w, k1w, v1w, o1w, Whi, Wlo);   // 0
    trans_kernel <<<dim3(8,8), 256>>>(k2w, k2t);                                // 1
    embed_kernel    <<<MR, 256>>>(wordid, mask, emb, H, Hhi, Hlo);              // 2
    initstate_kernel<<<BB, 256>>>(H, state);                                    // 3
    tcgemm3_kernel<<<dim3(mt,2), 256>>>(Hhi, Hlo, Whi, Wlo,                     // 4 (Ek,Ev)
                                        k1b, v1b, v1b, Ek, Ev, Ev, 1, 2, 2);

    for(int it = 0; it < 5; it++){
        // step 1
        tcgemm3_kernel<<<dim3(mt,3), 256>>>(Hhi, Hlo, Whi, Wlo,                 // 5 on iter 0
                                            q1b, k1b, v1b, Hq, Hk, Hv, 0, 1, 2);
        sgemm_kernel<<<dim3(4,2), 256>>>(state, k1w, k1b, Sk, v1w, v1b, Sv);
        attn1_kernel<<<MR, 256>>>(Hq, Hk, Hv, Ek, Ev, Sk, Sv, k1b, v1b, Ohi, Olo);
        tcgemm3_kernel<<<dim3(mt,1), 256>>>(Ohi, Olo, Whi, Wlo,
                                            o1b, o1b, o1b, Hq, Hq, Hq, 3, 3, 3);
        relu_ln_kernel<<<MR, 256>>>(Hq, ln1g, ln1bb, H, Hhi, Hlo);

        // step 2 (no big GEMMs)
        sgemm_kernel<<<dim3(4,1), 256>>>(state, q2w, q2b, q2, q2w, q2b, q2);
        qt_kernel   <<<dim3(BB,8), 256>>>(k2t, q2, qt);
        sc_kernel   <<<dim3(8,BB), 256>>>(H, qt, sc);
        mix_kernel  <<<BB, 256>>>(H, sc, hbar);
        vproj_kernel<<<BB, 256>>>(hbar, v2w, v2b, o2);
        sgemm_kernel<<<dim3(4,1), 256>>>(o2, o2w, o2b, q2, o2w, o2b, q2);
        relu_ln_kernel<<<BB, 256>>>(q2, ln2g, ln2bb, state, (__nv_bfloat16*)0, (__nv_bfloat16*)0);
    }

    logits_kernel<<<MR/8, 256>>>(H, linw, linb, out);
}